// round 11
// baseline (speedup 1.0000x reference)
#include <cuda_runtime.h>
#include <math.h>
#include <stdint.h>

// ---------------- problem constants (fixed shapes) ----------------
#define N_NODES 131072
#define EDIM    64
#define L0      262144
#define L1      524288
#define L2      393216
#define NROWS   (L0 + L1 + L2)   // 1179648
#define SCAN_BLOCKS 512          // N_NODES / 256

// ---------------- scratch (device globals; no cudaMalloc allowed) ----------
__device__ float g_msg[(size_t)NROWS * EDIM];     // node-sorted message rows
__device__ float g_mf [(size_t)N_NODES * EDIM];   // final max_msg per node
__device__ int   g_idx[NROWS];
__device__ int   g_cnt[N_NODES];                  // zero at load; reduce re-zeroes
__device__ int   g_start[N_NODES];
__device__ int   g_rank[N_NODES];                 // zeroed by scanBC each run
__device__ int   g_flag[N_NODES];                 // zero at load; reduce re-zeroes
__device__ int   g_bsum[SCAN_BLOCKS];

// ---------------- helpers ----------------
__device__ __forceinline__ float mishf(float x) {
    float sp = (x > 20.0f) ? x : log1pf(expf(x));
    return x * tanhf(sp);
}

// ---- packed f32x2 FMA (ptxas never emits FFMA2 from C++; PTX-only) ----
typedef unsigned long long ull;
__device__ __forceinline__ ull dup2(float w) {
    ull d;
    asm("mov.b64 %0, {%1, %1};" : "=l"(d) : "f"(w));
    return d;
}
__device__ __forceinline__ void fma2(ull& acc, ull x, ull w) {
    asm("fma.rn.f32x2 %0, %1, %2, %3;" : "=l"(acc) : "l"(x), "l"(w), "l"(acc));
}
__device__ __forceinline__ void unpack2(ull v, float& lo, float& hi) {
    asm("mov.b64 {%0, %1}, %2;" : "=f"(lo), "=f"(hi) : "l"(v));
}

// ---------------- 1. convert + histogram + rel0 flag (inline dtype detect) -
__global__ void convhist_kernel(const void* __restrict__ p0,
                                const void* __restrict__ p1,
                                const void* __restrict__ p2) {
    __shared__ int modeS;
    if (threadIdx.x < 32) {
        unsigned v = 0;
        if (threadIdx.x < 16) v = ((const unsigned*)p0)[threadIdx.x * 2 + 1];
        unsigned any = __ballot_sync(0xffffffffu, v != 0);
        if (threadIdx.x == 0) modeS = any ? 1 : 0;   // 1 = int32 data
    }
    __syncthreads();
    const int mode = modeS;

    int i = blockIdx.x * 256 + threadIdx.x;
    if (i >= NROWS) return;
    const void* p; int o;
    if      (i < L0)      { p = p0; o = i; }
    else if (i < L0 + L1) { p = p1; o = i - L0; }
    else                  { p = p2; o = i - L0 - L1; }
    int v;
    if (mode) v = ((const int*)p)[o];
    else      v = (int)(((const long long*)p)[o]);
    g_idx[i] = v;
    atomicAdd(&g_cnt[v], 1);
    if (i < L0) g_flag[v] = 1;   // racy identical writes: benign
}

// ---------------- 2a. per-block (256 nodes) sums ----------------
__global__ void scanA_kernel() {
    __shared__ int wsum[8];
    const int t = threadIdx.x;
    int v = g_cnt[blockIdx.x * 256 + t];
#pragma unroll
    for (int s = 16; s > 0; s >>= 1) v += __shfl_down_sync(0xffffffffu, v, s);
    if ((t & 31) == 0) wsum[t >> 5] = v;
    __syncthreads();
    if (t < 8) {
        int x = wsum[t];
#pragma unroll
        for (int s = 4; s > 0; s >>= 1) x += __shfl_down_sync(0xffu, x, s);
        if (t == 0) g_bsum[blockIdx.x] = x;
    }
}

// ---------------- 2b. base offset (masked reduce) + local scan --------------
__global__ void scanBC_kernel() {
    __shared__ int wsum[8];
    __shared__ int baseS;
    const int t = threadIdx.x;
    const int lane = t & 31, w = t >> 5;
    const int b = blockIdx.x;

    {
        int j0 = 2 * t, j1 = 2 * t + 1;
        int v = ((j0 < b) ? g_bsum[j0] : 0) + ((j1 < b) ? g_bsum[j1] : 0);
#pragma unroll
        for (int s = 16; s > 0; s >>= 1) v += __shfl_down_sync(0xffffffffu, v, s);
        if (lane == 0) wsum[w] = v;
        __syncthreads();
        if (t < 8) {
            int x = wsum[t];
#pragma unroll
            for (int s = 4; s > 0; s >>= 1) x += __shfl_down_sync(0xffu, x, s);
            if (t == 0) baseS = x;
        }
        __syncthreads();
    }

    const int i = b * 256 + t;
    int v = g_cnt[i];
    int inc = v;
#pragma unroll
    for (int s = 1; s < 32; s <<= 1) {
        int u = __shfl_up_sync(0xffffffffu, inc, s);
        if (lane >= s) inc += u;
    }
    __syncthreads();
    if (lane == 31) wsum[w] = inc;
    __syncthreads();
    if (t < 8) {
        int x = wsum[t];
#pragma unroll
        for (int s = 1; s < 8; s <<= 1) {
            int u = __shfl_up_sync(0xffu, x, s);
            if (t >= s) x += u;
        }
        wsum[t] = x;
    }
    __syncthreads();
    int wofs = (w == 0) ? 0 : wsum[w - 1];
    g_start[i] = baseS + wofs + inc - v;
    g_rank[i]  = 0;
}

// ---------------- 3. per-relation fused gather + MLP + sorted store --------
// blockDim.x == D/2: thread c owns two adjacent columns (2c, 2c+1).
// Register diet vs R10: x values and sorted positions live in smem only
// (re-read in epilogue/store), and __launch_bounds__ pins >=32 warps/SM.
template <int D, int A, int R>
__global__ void __launch_bounds__(D / 2, 2048 / D)
msg_kernel(const float* __restrict__ emb,
           const float* __restrict__ rw, const float* __restrict__ rb,
           const float* __restrict__ ow, const float* __restrict__ ob,
           int idx_ofs) {
    constexpr int R2 = R / 2;
    __shared__ __align__(16) float xs[R2][2 * D];
    __shared__ __align__(16) float zs[R2][2 * D];
    __shared__ int idxS[R * A];
    __shared__ int posS[R * A];
    const int c   = threadIdx.x;         // 0..D/2-1
    const int col = 2 * c;
    const int j   = col >> 6;            // which index within tuple
    const int e   = col & 63;            // even
    const int t0  = blockIdx.x * R;

    // one thread per message row: node + fused rank (segment order arbitrary)
    if (c < R * A) {
        int node = g_idx[idx_ofs + t0 * A + c];
        idxS[c] = node;
        posS[c] = g_start[node] + atomicAdd(&g_rank[node], 1);
    }
    __syncthreads();

    // gather row pairs straight into smem (no register arrays kept live)
#pragma unroll
    for (int p = 0; p < R2; ++p) {
        int n0 = idxS[(2 * p) * A + j];
        int n1 = idxS[(2 * p + 1) * A + j];
        float2 a = *(const float2*)&emb[(size_t)n0 * EDIM + e];
        float2 b = *(const float2*)&emb[(size_t)n1 * EDIM + e];
        *(float4*)&xs[p][4 * c] = make_float4(a.x, b.x, a.y, b.y);
    }
    __syncthreads();

    ull acc0[R2], acc1[R2];    // acc0: col, acc1: col+1 (rows packed in f32x2)
    // ---- h = x @ rw + rb ----
    {
        float2 b = *(const float2*)&rb[col];
#pragma unroll
        for (int p = 0; p < R2; ++p) { acc0[p] = dup2(b.x); acc1[p] = dup2(b.y); }
    }
#pragma unroll 4
    for (int k = 0; k < D; k += 2) {
        float2 wk0 = *(const float2*)&rw[(k + 0) * D + col];
        float2 wk1 = *(const float2*)&rw[(k + 1) * D + col];
        ull wA = dup2(wk0.x), wB = dup2(wk0.y);
        ull wC = dup2(wk1.x), wDd = dup2(wk1.y);
#pragma unroll
        for (int p = 0; p < R2; ++p) {
            ulonglong2 x2 = *(const ulonglong2*)&xs[p][2 * k];
            fma2(acc0[p], x2.x, wA);
            fma2(acc1[p], x2.x, wB);
            fma2(acc0[p], x2.y, wC);
            fma2(acc1[p], x2.y, wDd);
        }
    }
    // ---- z = x + mish(h) ----  (x re-read from smem, lane-local slot)
#pragma unroll
    for (int p = 0; p < R2; ++p) {
        float h00, h01, h10, h11;
        unpack2(acc0[p], h00, h01);   // (row2p,col), (row2p+1,col)
        unpack2(acc1[p], h10, h11);   // (row2p,col+1), (row2p+1,col+1)
        float4 xv = *(const float4*)&xs[p][4 * c];
        float4 v;
        v.x = xv.x + mishf(h00);
        v.y = xv.y + mishf(h01);
        v.z = xv.z + mishf(h10);
        v.w = xv.w + mishf(h11);
        *(float4*)&zs[p][4 * c] = v;
    }
    __syncthreads();

    // ---- out = z @ ow + ob ----
    {
        float2 b = *(const float2*)&ob[col];
#pragma unroll
        for (int p = 0; p < R2; ++p) { acc0[p] = dup2(b.x); acc1[p] = dup2(b.y); }
    }
#pragma unroll 4
    for (int k = 0; k < D; k += 2) {
        float2 wk0 = *(const float2*)&ow[(k + 0) * D + col];
        float2 wk1 = *(const float2*)&ow[(k + 1) * D + col];
        ull wA = dup2(wk0.x), wB = dup2(wk0.y);
        ull wC = dup2(wk1.x), wDd = dup2(wk1.y);
#pragma unroll
        for (int p = 0; p < R2; ++p) {
            ulonglong2 z2 = *(const ulonglong2*)&zs[p][2 * k];
            fma2(acc0[p], z2.x, wA);
            fma2(acc1[p], z2.x, wB);
            fma2(acc0[p], z2.y, wC);
            fma2(acc1[p], z2.y, wDd);
        }
    }

    // ---- store message rows at node-sorted slots (pos re-read from smem) --
#pragma unroll
    for (int p = 0; p < R2; ++p) {
        float o00, o01, o10, o11;
        unpack2(acc0[p], o00, o01);
        unpack2(acc1[p], o10, o11);
        int p0 = posS[(2 * p) * A + j];
        int p1 = posS[(2 * p + 1) * A + j];
        *(float2*)&g_msg[(size_t)p0 * EDIM + e] = make_float2(o00, o10);
        *(float2*)&g_msg[(size_t)p1 * EDIM + e] = make_float2(o01, o11);
    }
}

// ---------------- 4. segment softmax-reduce (single pass, online) ----------
__global__ void reduce_kernel() {
    int node = (blockIdx.x * blockDim.x + threadIdx.x) >> 5;
    if (node >= N_NODES) return;
    const int lane  = threadIdx.x & 31;
    const int start = g_start[node];
    const int end   = start + g_cnt[node];
    const float base = g_flag[node] ? -INFINITY : 0.0f;

    float m0 = base, m1 = base;
    float s0 = 0.0f, s1 = 0.0f;
    for (int r = start; r < end; ++r) {
        const float* row = &g_msg[(size_t)r * EDIM];
        float v0 = row[lane], v1 = row[lane + 32];
        float n0 = fmaxf(m0, v0), n1 = fmaxf(m1, v1);
        s0 = s0 * expf(12.0f * (m0 - n0)) + expf(12.0f * (v0 - n0));
        s1 = s1 * expf(12.0f * (m1 - n1)) + expf(12.0f * (v1 - n1));
        m0 = n0; m1 = n1;
    }
    s0 += 1e-16f; s1 += 1e-16f;
    size_t o = (size_t)node * EDIM;
    g_mf[o + lane]      = logf(s0) * (1.0f / 12.0f) + m0;
    g_mf[o + lane + 32] = logf(s1) * (1.0f / 12.0f) + m1;
    if (lane == 0) { g_cnt[node] = 0; g_flag[node] = 0; }   // ready for next replay
}

// ---------------- 5. node update MLP: [max_msg | emb] (128) -> 64 ----------
template <int R>
__global__ void update_kernel(const float* __restrict__ emb,
                              const float* __restrict__ rw, const float* __restrict__ rb,
                              const float* __restrict__ ow, const float* __restrict__ ob,
                              float* __restrict__ out) {
    constexpr int R2 = R / 2;
    __shared__ __align__(16) float xs[R2][256];
    __shared__ __align__(16) float zs[R2][256];
    const int c  = threadIdx.x;     // 0..127
    const int n0 = blockIdx.x * R;

    float xreg[R];
#pragma unroll
    for (int r = 0; r < R; ++r) {
        int node = n0 + r;
        float v = (c < 64) ? g_mf[(size_t)node * EDIM + c]
                           : emb[(size_t)node * EDIM + (c - 64)];
        xreg[r] = v;
        xs[r >> 1][2 * c + (r & 1)] = v;
    }
    __syncthreads();

    ull acc[R2];
#pragma unroll
    for (int p = 0; p < R2; ++p) acc[p] = dup2(rb[c]);
#pragma unroll 4
    for (int k = 0; k < 128; k += 2) {
        ull w0 = dup2(rw[(k + 0) * 128 + c]);
        ull w1 = dup2(rw[(k + 1) * 128 + c]);
#pragma unroll
        for (int p = 0; p < R2; ++p) {
            ulonglong2 x2 = *reinterpret_cast<const ulonglong2*>(&xs[p][2 * k]);
            fma2(acc[p], x2.x, w0);
            fma2(acc[p], x2.y, w1);
        }
    }
#pragma unroll
    for (int p = 0; p < R2; ++p) {
        float h0, h1;
        unpack2(acc[p], h0, h1);
        zs[p][2 * c + 0] = xreg[2 * p + 0] + mishf(h0);
        zs[p][2 * c + 1] = xreg[2 * p + 1] + mishf(h1);
    }
    __syncthreads();

    const int cc = c & 63;
#pragma unroll
    for (int t = 0; t < 4; ++t) {
        int p = (c >> 6) + 2 * t;
        ull a = dup2(ob[cc]);
#pragma unroll 4
        for (int k = 0; k < 128; k += 2) {
            ull w0 = dup2(ow[(k + 0) * 64 + cc]);
            ull w1 = dup2(ow[(k + 1) * 64 + cc]);
            ulonglong2 z2 = *reinterpret_cast<const ulonglong2*>(&zs[p][2 * k]);
            fma2(a, z2.x, w0);
            fma2(a, z2.y, w1);
        }
        float o0, o1;
        unpack2(a, o0, o1);
        out[(size_t)(n0 + 2 * p + 0) * EDIM + cc] = o0;
        out[(size_t)(n0 + 2 * p + 1) * EDIM + cc] = o1;
    }
}

// ---------------- launcher ----------------
extern "C" void kernel_launch(void* const* d_in, const int* in_sizes, int n_in,
                              void* d_out, int out_size) {
    const float* emb = (const float*)d_in[0];
    const void*  i0  = d_in[1];
    const void*  i1  = d_in[2];
    const void*  i2  = d_in[3];
    const float* r0rw = (const float*)d_in[4];
    const float* r0rb = (const float*)d_in[5];
    const float* r0ow = (const float*)d_in[6];
    const float* r0ob = (const float*)d_in[7];
    const float* r1rw = (const float*)d_in[8];
    const float* r1rb = (const float*)d_in[9];
    const float* r1ow = (const float*)d_in[10];
    const float* r1ob = (const float*)d_in[11];
    const float* r2rw = (const float*)d_in[12];
    const float* r2rb = (const float*)d_in[13];
    const float* r2ow = (const float*)d_in[14];
    const float* r2ob = (const float*)d_in[15];
    const float* urw  = (const float*)d_in[16];
    const float* urb  = (const float*)d_in[17];
    const float* uow  = (const float*)d_in[18];
    const float* uob  = (const float*)d_in[19];
    float* out = (float*)d_out;

    // prelude (3 launches)
    convhist_kernel<<<(NROWS + 255) / 256, 256>>>(i0, i1, i2);
    scanA_kernel<<<SCAN_BLOCKS, 256>>>();
    scanBC_kernel<<<SCAN_BLOCKS, 256>>>();

    // launch #4 = msg<128> (lands in the ncu capture window)
    msg_kernel<128, 2, 16><<<(L1 / 2) / 16,  64>>>(emb, r1rw, r1rb, r1ow, r1ob, L0);
    msg_kernel< 64, 1, 16><<<(L0 / 1) / 16,  32>>>(emb, r0rw, r0rb, r0ow, r0ob, 0);
    msg_kernel<192, 3, 16><<<(L2 / 3) / 16,  96>>>(emb, r2rw, r2rb, r2ow, r2ob, L0 + L1);

    // single-pass segment softmax-reduce, then node update
    reduce_kernel<<<(N_NODES * 32 + 255) / 256, 256>>>();
    update_kernel<16><<<N_NODES / 16, 128>>>(emb, urw, urb, uow, uob, out);
}

// round 12
// speedup vs baseline: 1.1849x; 1.1849x over previous
#include <cuda_runtime.h>
#include <math.h>
#include <stdint.h>

// ---------------- problem constants (fixed shapes) ----------------
#define N_NODES 131072
#define EDIM    64
#define L0      262144
#define L1      524288
#define L2      393216
#define NROWS   (L0 + L1 + L2)   // 1179648
#define SCAN_BLOCKS 512          // N_NODES / 256

// ---------------- scratch (device globals; no cudaMalloc allowed) ----------
__device__ float g_msg[(size_t)NROWS * EDIM];     // node-sorted message rows
__device__ float g_mf [(size_t)N_NODES * EDIM];   // final max_msg per node
__device__ int   g_idx[NROWS];
__device__ int   g_cnt[N_NODES];                  // zero at load; reduce re-zeroes
__device__ int   g_start[N_NODES];
__device__ int   g_rank[N_NODES];                 // zeroed by scanBC each run
__device__ int   g_flag[N_NODES];                 // zero at load; reduce re-zeroes
__device__ int   g_bsum[SCAN_BLOCKS];

// ---------------- helpers ----------------
__device__ __forceinline__ float mishf(float x) {
    float sp = (x > 20.0f) ? x : log1pf(expf(x));
    return x * tanhf(sp);
}

// ---- packed f32x2 FMA (ptxas never emits FFMA2 from C++; PTX-only) ----
typedef unsigned long long ull;
__device__ __forceinline__ ull dup2(float w) {
    ull d;
    asm("mov.b64 %0, {%1, %1};" : "=l"(d) : "f"(w));
    return d;
}
__device__ __forceinline__ void fma2(ull& acc, ull x, ull w) {
    asm("fma.rn.f32x2 %0, %1, %2, %3;" : "=l"(acc) : "l"(x), "l"(w), "l"(acc));
}
__device__ __forceinline__ void unpack2(ull v, float& lo, float& hi) {
    asm("mov.b64 {%0, %1}, %2;" : "=f"(lo), "=f"(hi) : "l"(v));
}

// ---------------- 1. convert + histogram + rel0 flag (inline dtype detect) -
__global__ void convhist_kernel(const void* __restrict__ p0,
                                const void* __restrict__ p1,
                                const void* __restrict__ p2) {
    __shared__ int modeS;
    if (threadIdx.x < 32) {
        unsigned v = 0;
        if (threadIdx.x < 16) v = ((const unsigned*)p0)[threadIdx.x * 2 + 1];
        unsigned any = __ballot_sync(0xffffffffu, v != 0);
        if (threadIdx.x == 0) modeS = any ? 1 : 0;   // 1 = int32 data
    }
    __syncthreads();
    const int mode = modeS;

    int i = blockIdx.x * 256 + threadIdx.x;
    if (i >= NROWS) return;
    const void* p; int o;
    if      (i < L0)      { p = p0; o = i; }
    else if (i < L0 + L1) { p = p1; o = i - L0; }
    else                  { p = p2; o = i - L0 - L1; }
    int v;
    if (mode) v = ((const int*)p)[o];
    else      v = (int)(((const long long*)p)[o]);
    g_idx[i] = v;
    atomicAdd(&g_cnt[v], 1);
    if (i < L0) g_flag[v] = 1;   // racy identical writes: benign
}

// ---------------- 2a. per-block (256 nodes) sums ----------------
__global__ void scanA_kernel() {
    __shared__ int wsum[8];
    const int t = threadIdx.x;
    int v = g_cnt[blockIdx.x * 256 + t];
#pragma unroll
    for (int s = 16; s > 0; s >>= 1) v += __shfl_down_sync(0xffffffffu, v, s);
    if ((t & 31) == 0) wsum[t >> 5] = v;
    __syncthreads();
    if (t < 8) {
        int x = wsum[t];
#pragma unroll
        for (int s = 4; s > 0; s >>= 1) x += __shfl_down_sync(0xffu, x, s);
        if (t == 0) g_bsum[blockIdx.x] = x;
    }
}

// ---------------- 2b. base offset (masked reduce) + local scan --------------
__global__ void scanBC_kernel() {
    __shared__ int wsum[8];
    __shared__ int baseS;
    const int t = threadIdx.x;
    const int lane = t & 31, w = t >> 5;
    const int b = blockIdx.x;

    {
        int j0 = 2 * t, j1 = 2 * t + 1;
        int v = ((j0 < b) ? g_bsum[j0] : 0) + ((j1 < b) ? g_bsum[j1] : 0);
#pragma unroll
        for (int s = 16; s > 0; s >>= 1) v += __shfl_down_sync(0xffffffffu, v, s);
        if (lane == 0) wsum[w] = v;
        __syncthreads();
        if (t < 8) {
            int x = wsum[t];
#pragma unroll
            for (int s = 4; s > 0; s >>= 1) x += __shfl_down_sync(0xffu, x, s);
            if (t == 0) baseS = x;
        }
        __syncthreads();
    }

    const int i = b * 256 + t;
    int v = g_cnt[i];
    int inc = v;
#pragma unroll
    for (int s = 1; s < 32; s <<= 1) {
        int u = __shfl_up_sync(0xffffffffu, inc, s);
        if (lane >= s) inc += u;
    }
    __syncthreads();
    if (lane == 31) wsum[w] = inc;
    __syncthreads();
    if (t < 8) {
        int x = wsum[t];
#pragma unroll
        for (int s = 1; s < 8; s <<= 1) {
            int u = __shfl_up_sync(0xffu, x, s);
            if (t >= s) x += u;
        }
        wsum[t] = x;
    }
    __syncthreads();
    int wofs = (w == 0) ? 0 : wsum[w - 1];
    g_start[i] = baseS + wofs + inc - v;
    g_rank[i]  = 0;
}

// ---------------- 3. per-relation fused gather + MLP + sorted store --------
// 1-column layout (proven fastest): blockDim.x == D, thread c owns column c.
// Occupancy fix vs R7: pos[] and xreg[] register arrays removed (re-read from
// smem when needed) + __launch_bounds__ pins ~32 warps/SM (was 24).
// Row pairs packed into f32x2 lanes: xs[p][2k+h] = element k of rows (2p,2p+1).
template <int D, int A, int R>
__global__ void __launch_bounds__(D, 1024 / D)
msg_kernel(const float* __restrict__ emb,
           const float* __restrict__ rw, const float* __restrict__ rb,
           const float* __restrict__ ow, const float* __restrict__ ob,
           int idx_ofs) {
    constexpr int R2 = R / 2;
    __shared__ __align__(16) float xs[R2][2 * D];
    __shared__ __align__(16) float zs[R2][2 * D];
    __shared__ int idxS[R * A];
    __shared__ int posS[R * A];
    const int c  = threadIdx.x;          // column 0..D-1
    const int j  = c >> 6;               // which index within tuple
    const int e  = c & 63;
    const int t0 = blockIdx.x * R;

    // one thread per message row: node + fused rank (segment order arbitrary)
    if (c < R * A) {
        int node = g_idx[idx_ofs + t0 * A + c];
        idxS[c] = node;
        posS[c] = g_start[node] + atomicAdd(&g_rank[node], 1);
    }
    __syncthreads();

    // gather straight into smem (no long-lived register arrays)
#pragma unroll
    for (int r = 0; r < R; ++r) {
        int node = idxS[r * A + j];
        xs[r >> 1][2 * c + (r & 1)] = emb[(size_t)node * EDIM + e];
    }
    __syncthreads();

    ull acc[R2];
    // ---- h = x @ rw + rb ----
#pragma unroll
    for (int p = 0; p < R2; ++p) acc[p] = dup2(rb[c]);
#pragma unroll 4
    for (int k = 0; k < D; k += 2) {
        ull w0 = dup2(rw[(k + 0) * D + c]);
        ull w1 = dup2(rw[(k + 1) * D + c]);
#pragma unroll
        for (int p = 0; p < R2; ++p) {
            ulonglong2 x2 = *reinterpret_cast<const ulonglong2*>(&xs[p][2 * k]);
            fma2(acc[p], x2.x, w0);
            fma2(acc[p], x2.y, w1);
        }
    }
    // ---- z = x + mish(h) ----  (x re-read from smem, lane-local 8B)
#pragma unroll
    for (int p = 0; p < R2; ++p) {
        float h0, h1;
        unpack2(acc[p], h0, h1);
        float2 xv = *(const float2*)&xs[p][2 * c];
        zs[p][2 * c + 0] = xv.x + mishf(h0);
        zs[p][2 * c + 1] = xv.y + mishf(h1);
    }
    __syncthreads();

    // ---- out = z @ ow + ob ----
#pragma unroll
    for (int p = 0; p < R2; ++p) acc[p] = dup2(ob[c]);
#pragma unroll 4
    for (int k = 0; k < D; k += 2) {
        ull w0 = dup2(ow[(k + 0) * D + c]);
        ull w1 = dup2(ow[(k + 1) * D + c]);
#pragma unroll
        for (int p = 0; p < R2; ++p) {
            ulonglong2 z2 = *reinterpret_cast<const ulonglong2*>(&zs[p][2 * k]);
            fma2(acc[p], z2.x, w0);
            fma2(acc[p], z2.y, w1);
        }
    }

    // ---- store message rows at node-sorted slots (pos re-read from smem) --
#pragma unroll
    for (int p = 0; p < R2; ++p) {
        float o0, o1;
        unpack2(acc[p], o0, o1);
        int p0 = posS[(2 * p) * A + j];
        int p1 = posS[(2 * p + 1) * A + j];
        g_msg[(size_t)p0 * EDIM + e] = o0;
        g_msg[(size_t)p1 * EDIM + e] = o1;
    }
}

// ---------------- 4. segment softmax-reduce (single pass, online) ----------
__global__ void reduce_kernel() {
    int node = (blockIdx.x * blockDim.x + threadIdx.x) >> 5;
    if (node >= N_NODES) return;
    const int lane  = threadIdx.x & 31;
    const int start = g_start[node];
    const int end   = start + g_cnt[node];
    const float base = g_flag[node] ? -INFINITY : 0.0f;

    float m0 = base, m1 = base;
    float s0 = 0.0f, s1 = 0.0f;
    for (int r = start; r < end; ++r) {
        const float* row = &g_msg[(size_t)r * EDIM];
        float v0 = row[lane], v1 = row[lane + 32];
        float n0 = fmaxf(m0, v0), n1 = fmaxf(m1, v1);
        s0 = s0 * expf(12.0f * (m0 - n0)) + expf(12.0f * (v0 - n0));
        s1 = s1 * expf(12.0f * (m1 - n1)) + expf(12.0f * (v1 - n1));
        m0 = n0; m1 = n1;
    }
    s0 += 1e-16f; s1 += 1e-16f;
    size_t o = (size_t)node * EDIM;
    g_mf[o + lane]      = logf(s0) * (1.0f / 12.0f) + m0;
    g_mf[o + lane + 32] = logf(s1) * (1.0f / 12.0f) + m1;
    if (lane == 0) { g_cnt[node] = 0; g_flag[node] = 0; }   // ready for next replay
}

// ---------------- 5. node update MLP: [max_msg | emb] (128) -> 64 ----------
template <int R>
__global__ void update_kernel(const float* __restrict__ emb,
                              const float* __restrict__ rw, const float* __restrict__ rb,
                              const float* __restrict__ ow, const float* __restrict__ ob,
                              float* __restrict__ out) {
    constexpr int R2 = R / 2;
    __shared__ __align__(16) float xs[R2][256];
    __shared__ __align__(16) float zs[R2][256];
    const int c  = threadIdx.x;     // 0..127
    const int n0 = blockIdx.x * R;

#pragma unroll
    for (int r = 0; r < R; ++r) {
        int node = n0 + r;
        float v = (c < 64) ? g_mf[(size_t)node * EDIM + c]
                           : emb[(size_t)node * EDIM + (c - 64)];
        xs[r >> 1][2 * c + (r & 1)] = v;
    }
    __syncthreads();

    ull acc[R2];
#pragma unroll
    for (int p = 0; p < R2; ++p) acc[p] = dup2(rb[c]);
#pragma unroll 4
    for (int k = 0; k < 128; k += 2) {
        ull w0 = dup2(rw[(k + 0) * 128 + c]);
        ull w1 = dup2(rw[(k + 1) * 128 + c]);
#pragma unroll
        for (int p = 0; p < R2; ++p) {
            ulonglong2 x2 = *reinterpret_cast<const ulonglong2*>(&xs[p][2 * k]);
            fma2(acc[p], x2.x, w0);
            fma2(acc[p], x2.y, w1);
        }
    }
#pragma unroll
    for (int p = 0; p < R2; ++p) {
        float h0, h1;
        unpack2(acc[p], h0, h1);
        float2 xv = *(const float2*)&xs[p][2 * c];
        zs[p][2 * c + 0] = xv.x + mishf(h0);
        zs[p][2 * c + 1] = xv.y + mishf(h1);
    }
    __syncthreads();

    const int cc = c & 63;
#pragma unroll
    for (int t = 0; t < 4; ++t) {
        int p = (c >> 6) + 2 * t;
        ull a = dup2(ob[cc]);
#pragma unroll 4
        for (int k = 0; k < 128; k += 2) {
            ull w0 = dup2(ow[(k + 0) * 64 + cc]);
            ull w1 = dup2(ow[(k + 1) * 64 + cc]);
            ulonglong2 z2 = *reinterpret_cast<const ulonglong2*>(&zs[p][2 * k]);
            fma2(a, z2.x, w0);
            fma2(a, z2.y, w1);
        }
        float o0, o1;
        unpack2(a, o0, o1);
        out[(size_t)(n0 + 2 * p + 0) * EDIM + cc] = o0;
        out[(size_t)(n0 + 2 * p + 1) * EDIM + cc] = o1;
    }
}

// ---------------- launcher ----------------
extern "C" void kernel_launch(void* const* d_in, const int* in_sizes, int n_in,
                              void* d_out, int out_size) {
    const float* emb = (const float*)d_in[0];
    const void*  i0  = d_in[1];
    const void*  i1  = d_in[2];
    const void*  i2  = d_in[3];
    const float* r0rw = (const float*)d_in[4];
    const float* r0rb = (const float*)d_in[5];
    const float* r0ow = (const float*)d_in[6];
    const float* r0ob = (const float*)d_in[7];
    const float* r1rw = (const float*)d_in[8];
    const float* r1rb = (const float*)d_in[9];
    const float* r1ow = (const float*)d_in[10];
    const float* r1ob = (const float*)d_in[11];
    const float* r2rw = (const float*)d_in[12];
    const float* r2rb = (const float*)d_in[13];
    const float* r2ow = (const float*)d_in[14];
    const float* r2ob = (const float*)d_in[15];
    const float* urw  = (const float*)d_in[16];
    const float* urb  = (const float*)d_in[17];
    const float* uow  = (const float*)d_in[18];
    const float* uob  = (const float*)d_in[19];
    float* out = (float*)d_out;

    // prelude (3 launches)
    convhist_kernel<<<(NROWS + 255) / 256, 256>>>(i0, i1, i2);
    scanA_kernel<<<SCAN_BLOCKS, 256>>>();
    scanBC_kernel<<<SCAN_BLOCKS, 256>>>();

    // launch #4 = msg<128> (lands in the ncu capture window)
    msg_kernel<128, 2, 16><<<(L1 / 2) / 16, 128>>>(emb, r1rw, r1rb, r1ow, r1ob, L0);
    msg_kernel< 64, 1, 16><<<(L0 / 1) / 16,  64>>>(emb, r0rw, r0rb, r0ow, r0ob, 0);
    msg_kernel<192, 3, 16><<<(L2 / 3) / 16, 192>>>(emb, r2rw, r2rb, r2ow, r2ob, L0 + L1);

    // single-pass segment softmax-reduce, then node update
    reduce_kernel<<<(N_NODES * 32 + 255) / 256, 256>>>();
    update_kernel<16><<<N_NODES / 16, 128>>>(emb, urw, urb, uow, uob, out);
}

// round 13
// speedup vs baseline: 1.5467x; 1.3054x over previous
#include <cuda_runtime.h>
#include <math.h>
#include <stdint.h>

// ---------------- problem constants (fixed shapes) ----------------
#define N_NODES 131072
#define EDIM    64
#define L0      262144
#define L1      524288
#define L2      393216
#define NROWS   (L0 + L1 + L2)   // 1179648
#define SCAN_BLOCKS 512          // N_NODES / 256

// ---------------- scratch (device globals; no cudaMalloc allowed) ----------
__device__ float g_msg[(size_t)NROWS * EDIM];     // node-sorted message rows
__device__ float g_mf [(size_t)N_NODES * EDIM];   // final max_msg per node
__device__ int   g_idx[NROWS];
__device__ int   g_cnt[N_NODES];                  // zero at load; reduce re-zeroes
__device__ int   g_start[N_NODES];
__device__ int   g_rank[N_NODES];                 // zeroed by scanBC each run
__device__ int   g_flag[N_NODES];                 // zero at load; reduce re-zeroes
__device__ int   g_bsum[SCAN_BLOCKS];

// ---------------- helpers ----------------
__device__ __forceinline__ float mishf(float x) {
    float sp = (x > 20.0f) ? x : log1pf(expf(x));
    return x * tanhf(sp);
}

// ---- packed f32x2 FMA (ptxas never emits FFMA2 from C++; PTX-only) ----
typedef unsigned long long ull;
__device__ __forceinline__ ull dup2(float w) {
    ull d;
    asm("mov.b64 %0, {%1, %1};" : "=l"(d) : "f"(w));
    return d;
}
__device__ __forceinline__ void fma2(ull& acc, ull x, ull w) {
    asm("fma.rn.f32x2 %0, %1, %2, %3;" : "=l"(acc) : "l"(x), "l"(w), "l"(acc));
}
__device__ __forceinline__ void unpack2(ull v, float& lo, float& hi) {
    asm("mov.b64 {%0, %1}, %2;" : "=f"(lo), "=f"(hi) : "l"(v));
}

// ---------------- 1. convert + histogram + rel0 flag (inline dtype detect) -
__global__ void convhist_kernel(const void* __restrict__ p0,
                                const void* __restrict__ p1,
                                const void* __restrict__ p2) {
    __shared__ int modeS;
    if (threadIdx.x < 32) {
        unsigned v = 0;
        if (threadIdx.x < 16) v = ((const unsigned*)p0)[threadIdx.x * 2 + 1];
        unsigned any = __ballot_sync(0xffffffffu, v != 0);
        if (threadIdx.x == 0) modeS = any ? 1 : 0;   // 1 = int32 data
    }
    __syncthreads();
    const int mode = modeS;

    int i = blockIdx.x * 256 + threadIdx.x;
    if (i >= NROWS) return;
    const void* p; int o;
    if      (i < L0)      { p = p0; o = i; }
    else if (i < L0 + L1) { p = p1; o = i - L0; }
    else                  { p = p2; o = i - L0 - L1; }
    int v;
    if (mode) v = ((const int*)p)[o];
    else      v = (int)(((const long long*)p)[o]);
    g_idx[i] = v;
    atomicAdd(&g_cnt[v], 1);
    if (i < L0) g_flag[v] = 1;   // racy identical writes: benign
}

// ---------------- 2a. per-block (256 nodes) sums ----------------
__global__ void scanA_kernel() {
    __shared__ int wsum[8];
    const int t = threadIdx.x;
    int v = g_cnt[blockIdx.x * 256 + t];
#pragma unroll
    for (int s = 16; s > 0; s >>= 1) v += __shfl_down_sync(0xffffffffu, v, s);
    if ((t & 31) == 0) wsum[t >> 5] = v;
    __syncthreads();
    if (t < 8) {
        int x = wsum[t];
#pragma unroll
        for (int s = 4; s > 0; s >>= 1) x += __shfl_down_sync(0xffu, x, s);
        if (t == 0) g_bsum[blockIdx.x] = x;
    }
}

// ---------------- 2b. base offset (masked reduce) + local scan --------------
__global__ void scanBC_kernel() {
    __shared__ int wsum[8];
    __shared__ int baseS;
    const int t = threadIdx.x;
    const int lane = t & 31, w = t >> 5;
    const int b = blockIdx.x;

    {
        int j0 = 2 * t, j1 = 2 * t + 1;
        int v = ((j0 < b) ? g_bsum[j0] : 0) + ((j1 < b) ? g_bsum[j1] : 0);
#pragma unroll
        for (int s = 16; s > 0; s >>= 1) v += __shfl_down_sync(0xffffffffu, v, s);
        if (lane == 0) wsum[w] = v;
        __syncthreads();
        if (t < 8) {
            int x = wsum[t];
#pragma unroll
            for (int s = 4; s > 0; s >>= 1) x += __shfl_down_sync(0xffu, x, s);
            if (t == 0) baseS = x;
        }
        __syncthreads();
    }

    const int i = b * 256 + t;
    int v = g_cnt[i];
    int inc = v;
#pragma unroll
    for (int s = 1; s < 32; s <<= 1) {
        int u = __shfl_up_sync(0xffffffffu, inc, s);
        if (lane >= s) inc += u;
    }
    __syncthreads();
    if (lane == 31) wsum[w] = inc;
    __syncthreads();
    if (t < 8) {
        int x = wsum[t];
#pragma unroll
        for (int s = 1; s < 8; s <<= 1) {
            int u = __shfl_up_sync(0xffu, x, s);
            if (t >= s) x += u;
        }
        wsum[t] = x;
    }
    __syncthreads();
    int wofs = (w == 0) ? 0 : wsum[w - 1];
    g_start[i] = baseS + wofs + inc - v;
    g_rank[i]  = 0;
}

// ---------------- 3. per-relation fused gather + MLP + sorted store --------
// Two 16-row tiles per block (blockDim = D): threads [0, D/2) process tile 0,
// [D/2, D) tile 1. Each thread owns two adjacent columns (2c2, 2c2+1), so one
// broadcast LDS.128 feeds 32 fma2 (2x the 1-col kernel). z overwrites xs in
// place after a barrier (halves smem -> 8 blocks/SM at D=128).
template <int D, int A, int R>
__global__ void __launch_bounds__(D, 1024 / D)
msg_kernel(const float* __restrict__ emb,
           const float* __restrict__ rw, const float* __restrict__ rb,
           const float* __restrict__ ow, const float* __restrict__ ob,
           int idx_ofs) {
    constexpr int R2   = R / 2;
    constexpr int HALF = D / 2;
    __shared__ __align__(16) float xs[2][R2][2 * D];   // x, then z in-place
    __shared__ int idxS[2 * R * A];
    __shared__ int posS[2 * R * A];
    const int tid   = threadIdx.x;
    const int half  = tid / HALF;        // which tile
    const int c2    = tid % HALF;
    const int col   = 2 * c2;
    const int j     = col >> 6;          // which index within tuple
    const int e     = col & 63;          // even
    const int t0    = blockIdx.x * (2 * R);
    const int rbase = half * R;          // local tuple base for this tile

    // one thread per message row: node + fused rank (segment order arbitrary)
    if (tid < 2 * R * A) {
        int node = g_idx[idx_ofs + t0 * A + tid];
        idxS[tid] = node;
        posS[tid] = g_start[node] + atomicAdd(&g_rank[node], 1);
    }
    __syncthreads();

    // gather row pairs into this tile's smem slice
#pragma unroll
    for (int p = 0; p < R2; ++p) {
        int n0 = idxS[(rbase + 2 * p) * A + j];
        int n1 = idxS[(rbase + 2 * p + 1) * A + j];
        float2 a = *(const float2*)&emb[(size_t)n0 * EDIM + e];
        float2 b = *(const float2*)&emb[(size_t)n1 * EDIM + e];
        *(float4*)&xs[half][p][4 * c2] = make_float4(a.x, b.x, a.y, b.y);
    }
    __syncthreads();

    ull acc0[R2], acc1[R2];    // acc0: col, acc1: col+1 (rows packed in f32x2)
    // ---- h = x @ rw + rb ----
    {
        float2 b = *(const float2*)&rb[col];
#pragma unroll
        for (int p = 0; p < R2; ++p) { acc0[p] = dup2(b.x); acc1[p] = dup2(b.y); }
    }
#pragma unroll 4
    for (int k = 0; k < D; k += 2) {
        float2 wk0 = *(const float2*)&rw[(k + 0) * D + col];
        float2 wk1 = *(const float2*)&rw[(k + 1) * D + col];
        ull wA = dup2(wk0.x), wB = dup2(wk0.y);
        ull wC = dup2(wk1.x), wDd = dup2(wk1.y);
#pragma unroll
        for (int p = 0; p < R2; ++p) {
            ulonglong2 x2 = *(const ulonglong2*)&xs[half][p][2 * k];
            fma2(acc0[p], x2.x, wA);
            fma2(acc1[p], x2.x, wB);
            fma2(acc0[p], x2.y, wC);
            fma2(acc1[p], x2.y, wDd);
        }
    }
    __syncthreads();   // all GEMM1 reads of xs complete before overwrite

    // ---- z = x + mish(h), written in place over xs ----
#pragma unroll
    for (int p = 0; p < R2; ++p) {
        float h00, h01, h10, h11;
        unpack2(acc0[p], h00, h01);   // (row2p,col), (row2p+1,col)
        unpack2(acc1[p], h10, h11);   // (row2p,col+1), (row2p+1,col+1)
        float4 xv = *(const float4*)&xs[half][p][4 * c2];
        float4 v;
        v.x = xv.x + mishf(h00);
        v.y = xv.y + mishf(h01);
        v.z = xv.z + mishf(h10);
        v.w = xv.w + mishf(h11);
        *(float4*)&xs[half][p][4 * c2] = v;
    }
    __syncthreads();

    // ---- out = z @ ow + ob ----
    {
        float2 b = *(const float2*)&ob[col];
#pragma unroll
        for (int p = 0; p < R2; ++p) { acc0[p] = dup2(b.x); acc1[p] = dup2(b.y); }
    }
#pragma unroll 4
    for (int k = 0; k < D; k += 2) {
        float2 wk0 = *(const float2*)&ow[(k + 0) * D + col];
        float2 wk1 = *(const float2*)&ow[(k + 1) * D + col];
        ull wA = dup2(wk0.x), wB = dup2(wk0.y);
        ull wC = dup2(wk1.x), wDd = dup2(wk1.y);
#pragma unroll
        for (int p = 0; p < R2; ++p) {
            ulonglong2 z2 = *(const ulonglong2*)&xs[half][p][2 * k];
            fma2(acc0[p], z2.x, wA);
            fma2(acc1[p], z2.x, wB);
            fma2(acc0[p], z2.y, wC);
            fma2(acc1[p], z2.y, wDd);
        }
    }

    // ---- store message rows at node-sorted slots (pos from smem) ----
#pragma unroll
    for (int p = 0; p < R2; ++p) {
        float o00, o01, o10, o11;
        unpack2(acc0[p], o00, o01);
        unpack2(acc1[p], o10, o11);
        int p0 = posS[(rbase + 2 * p) * A + j];
        int p1 = posS[(rbase + 2 * p + 1) * A + j];
        *(float2*)&g_msg[(size_t)p0 * EDIM + e] = make_float2(o00, o10);
        *(float2*)&g_msg[(size_t)p1 * EDIM + e] = make_float2(o01, o11);
    }
}

// ---------------- 4. segment softmax-reduce (single pass, online) ----------
__global__ void reduce_kernel() {
    int node = (blockIdx.x * blockDim.x + threadIdx.x) >> 5;
    if (node >= N_NODES) return;
    const int lane  = threadIdx.x & 31;
    const int start = g_start[node];
    const int end   = start + g_cnt[node];
    const float base = g_flag[node] ? -INFINITY : 0.0f;

    float m0 = base, m1 = base;
    float s0 = 0.0f, s1 = 0.0f;
    for (int r = start; r < end; ++r) {
        const float* row = &g_msg[(size_t)r * EDIM];
        float v0 = row[lane], v1 = row[lane + 32];
        float n0 = fmaxf(m0, v0), n1 = fmaxf(m1, v1);
        s0 = s0 * expf(12.0f * (m0 - n0)) + expf(12.0f * (v0 - n0));
        s1 = s1 * expf(12.0f * (m1 - n1)) + expf(12.0f * (v1 - n1));
        m0 = n0; m1 = n1;
    }
    s0 += 1e-16f; s1 += 1e-16f;
    size_t o = (size_t)node * EDIM;
    g_mf[o + lane]      = logf(s0) * (1.0f / 12.0f) + m0;
    g_mf[o + lane + 32] = logf(s1) * (1.0f / 12.0f) + m1;
    if (lane == 0) { g_cnt[node] = 0; g_flag[node] = 0; }   // ready for next replay
}

// ---------------- 5. node update MLP: [max_msg | emb] (128) -> 64 ----------
template <int R>
__global__ void update_kernel(const float* __restrict__ emb,
                              const float* __restrict__ rw, const float* __restrict__ rb,
                              const float* __restrict__ ow, const float* __restrict__ ob,
                              float* __restrict__ out) {
    constexpr int R2 = R / 2;
    __shared__ __align__(16) float xs[R2][256];
    __shared__ __align__(16) float zs[R2][256];
    const int c  = threadIdx.x;     // 0..127
    const int n0 = blockIdx.x * R;

#pragma unroll
    for (int r = 0; r < R; ++r) {
        int node = n0 + r;
        float v = (c < 64) ? g_mf[(size_t)node * EDIM + c]
                           : emb[(size_t)node * EDIM + (c - 64)];
        xs[r >> 1][2 * c + (r & 1)] = v;
    }
    __syncthreads();

    ull acc[R2];
#pragma unroll
    for (int p = 0; p < R2; ++p) acc[p] = dup2(rb[c]);
#pragma unroll 4
    for (int k = 0; k < 128; k += 2) {
        ull w0 = dup2(rw[(k + 0) * 128 + c]);
        ull w1 = dup2(rw[(k + 1) * 128 + c]);
#pragma unroll
        for (int p = 0; p < R2; ++p) {
            ulonglong2 x2 = *reinterpret_cast<const ulonglong2*>(&xs[p][2 * k]);
            fma2(acc[p], x2.x, w0);
            fma2(acc[p], x2.y, w1);
        }
    }
#pragma unroll
    for (int p = 0; p < R2; ++p) {
        float h0, h1;
        unpack2(acc[p], h0, h1);
        float2 xv = *(const float2*)&xs[p][2 * c];
        zs[p][2 * c + 0] = xv.x + mishf(h0);
        zs[p][2 * c + 1] = xv.y + mishf(h1);
    }
    __syncthreads();

    const int cc = c & 63;
#pragma unroll
    for (int t = 0; t < 4; ++t) {
        int p = (c >> 6) + 2 * t;
        ull a = dup2(ob[cc]);
#pragma unroll 4
        for (int k = 0; k < 128; k += 2) {
            ull w0 = dup2(ow[(k + 0) * 64 + cc]);
            ull w1 = dup2(ow[(k + 1) * 64 + cc]);
            ulonglong2 z2 = *reinterpret_cast<const ulonglong2*>(&zs[p][2 * k]);
            fma2(a, z2.x, w0);
            fma2(a, z2.y, w1);
        }
        float o0, o1;
        unpack2(a, o0, o1);
        out[(size_t)(n0 + 2 * p + 0) * EDIM + cc] = o0;
        out[(size_t)(n0 + 2 * p + 1) * EDIM + cc] = o1;
    }
}

// ---------------- launcher ----------------
extern "C" void kernel_launch(void* const* d_in, const int* in_sizes, int n_in,
                              void* d_out, int out_size) {
    const float* emb = (const float*)d_in[0];
    const void*  i0  = d_in[1];
    const void*  i1  = d_in[2];
    const void*  i2  = d_in[3];
    const float* r0rw = (const float*)d_in[4];
    const float* r0rb = (const float*)d_in[5];
    const float* r0ow = (const float*)d_in[6];
    const float* r0ob = (const float*)d_in[7];
    const float* r1rw = (const float*)d_in[8];
    const float* r1rb = (const float*)d_in[9];
    const float* r1ow = (const float*)d_in[10];
    const float* r1ob = (const float*)d_in[11];
    const float* r2rw = (const float*)d_in[12];
    const float* r2rb = (const float*)d_in[13];
    const float* r2ow = (const float*)d_in[14];
    const float* r2ob = (const float*)d_in[15];
    const float* urw  = (const float*)d_in[16];
    const float* urb  = (const float*)d_in[17];
    const float* uow  = (const float*)d_in[18];
    const float* uob  = (const float*)d_in[19];
    float* out = (float*)d_out;

    // prelude (3 launches)
    convhist_kernel<<<(NROWS + 255) / 256, 256>>>(i0, i1, i2);
    scanA_kernel<<<SCAN_BLOCKS, 256>>>();
    scanBC_kernel<<<SCAN_BLOCKS, 256>>>();

    // launch #4 = msg<128> (lands in the ncu capture window)
    // each block covers 2*R = 32 tuples
    msg_kernel<128, 2, 16><<<(L1 / 2) / 32, 128>>>(emb, r1rw, r1rb, r1ow, r1ob, L0);
    msg_kernel< 64, 1, 16><<<(L0 / 1) / 32,  64>>>(emb, r0rw, r0rb, r0ow, r0ob, 0);
    msg_kernel<192, 3, 16><<<(L2 / 3) / 32, 192>>>(emb, r2rw, r2rb, r2ow, r2ob, L0 + L1);

    // single-pass segment softmax-reduce, then node update
    reduce_kernel<<<(N_NODES * 32 + 255) / 256, 256>>>();
    update_kernel<16><<<N_NODES / 16, 128>>>(emb, urw, urb, uow, uob, out);
}

// round 14
// speedup vs baseline: 1.5660x; 1.0125x over previous
#include <cuda_runtime.h>
#include <math.h>
#include <stdint.h>

// ---------------- problem constants (fixed shapes) ----------------
#define N_NODES 131072
#define EDIM    64
#define L0      262144
#define L1      524288
#define L2      393216
#define NROWS   (L0 + L1 + L2)   // 1179648
#define SCAN_BLOCKS 512          // N_NODES / 256

// ---------------- scratch (device globals; no cudaMalloc allowed) ----------
__device__ float g_msg[(size_t)NROWS * EDIM];     // node-sorted message rows
__device__ float g_mf [(size_t)N_NODES * EDIM];   // final max_msg per node
__device__ int   g_idx[NROWS];
__device__ int   g_cnt[N_NODES];                  // zero at load; reduce re-zeroes
__device__ int   g_start[N_NODES];
__device__ int   g_rank[N_NODES];                 // zeroed by scanBC each run
__device__ int   g_flag[N_NODES];                 // zero at load; reduce re-zeroes
__device__ int   g_bsum[SCAN_BLOCKS];

// ---------------- helpers ----------------
__device__ __forceinline__ float mishf(float x) {
    float sp = (x > 20.0f) ? x : log1pf(expf(x));
    return x * tanhf(sp);
}

// ---- packed f32x2 FMA (ptxas never emits FFMA2 from C++; PTX-only) ----
typedef unsigned long long ull;
__device__ __forceinline__ ull dup2(float w) {
    ull d;
    asm("mov.b64 %0, {%1, %1};" : "=l"(d) : "f"(w));
    return d;
}
__device__ __forceinline__ void fma2(ull& acc, ull x, ull w) {
    asm("fma.rn.f32x2 %0, %1, %2, %3;" : "=l"(acc) : "l"(x), "l"(w), "l"(acc));
}
__device__ __forceinline__ void unpack2(ull v, float& lo, float& hi) {
    asm("mov.b64 {%0, %1}, %2;" : "=f"(lo), "=f"(hi) : "l"(v));
}

// ---------------- 1. convert + histogram + rel0 flag (inline dtype detect) -
__global__ void convhist_kernel(const void* __restrict__ p0,
                                const void* __restrict__ p1,
                                const void* __restrict__ p2) {
    __shared__ int modeS;
    if (threadIdx.x < 32) {
        unsigned v = 0;
        if (threadIdx.x < 16) v = ((const unsigned*)p0)[threadIdx.x * 2 + 1];
        unsigned any = __ballot_sync(0xffffffffu, v != 0);
        if (threadIdx.x == 0) modeS = any ? 1 : 0;   // 1 = int32 data
    }
    __syncthreads();
    const int mode = modeS;

    int i = blockIdx.x * 256 + threadIdx.x;
    if (i >= NROWS) return;
    const void* p; int o;
    if      (i < L0)      { p = p0; o = i; }
    else if (i < L0 + L1) { p = p1; o = i - L0; }
    else                  { p = p2; o = i - L0 - L1; }
    int v;
    if (mode) v = ((const int*)p)[o];
    else      v = (int)(((const long long*)p)[o]);
    g_idx[i] = v;
    atomicAdd(&g_cnt[v], 1);
    if (i < L0) g_flag[v] = 1;   // racy identical writes: benign
}

// ---------------- 2a. per-block (256 nodes) sums ----------------
__global__ void scanA_kernel() {
    __shared__ int wsum[8];
    const int t = threadIdx.x;
    int v = g_cnt[blockIdx.x * 256 + t];
#pragma unroll
    for (int s = 16; s > 0; s >>= 1) v += __shfl_down_sync(0xffffffffu, v, s);
    if ((t & 31) == 0) wsum[t >> 5] = v;
    __syncthreads();
    if (t < 8) {
        int x = wsum[t];
#pragma unroll
        for (int s = 4; s > 0; s >>= 1) x += __shfl_down_sync(0xffu, x, s);
        if (t == 0) g_bsum[blockIdx.x] = x;
    }
}

// ---------------- 2b. base offset (masked reduce) + local scan --------------
__global__ void scanBC_kernel() {
    __shared__ int wsum[8];
    __shared__ int baseS;
    const int t = threadIdx.x;
    const int lane = t & 31, w = t >> 5;
    const int b = blockIdx.x;

    {
        int j0 = 2 * t, j1 = 2 * t + 1;
        int v = ((j0 < b) ? g_bsum[j0] : 0) + ((j1 < b) ? g_bsum[j1] : 0);
#pragma unroll
        for (int s = 16; s > 0; s >>= 1) v += __shfl_down_sync(0xffffffffu, v, s);
        if (lane == 0) wsum[w] = v;
        __syncthreads();
        if (t < 8) {
            int x = wsum[t];
#pragma unroll
            for (int s = 4; s > 0; s >>= 1) x += __shfl_down_sync(0xffu, x, s);
            if (t == 0) baseS = x;
        }
        __syncthreads();
    }

    const int i = b * 256 + t;
    int v = g_cnt[i];
    int inc = v;
#pragma unroll
    for (int s = 1; s < 32; s <<= 1) {
        int u = __shfl_up_sync(0xffffffffu, inc, s);
        if (lane >= s) inc += u;
    }
    __syncthreads();
    if (lane == 31) wsum[w] = inc;
    __syncthreads();
    if (t < 8) {
        int x = wsum[t];
#pragma unroll
        for (int s = 1; s < 8; s <<= 1) {
            int u = __shfl_up_sync(0xffu, x, s);
            if (t >= s) x += u;
        }
        wsum[t] = x;
    }
    __syncthreads();
    int wofs = (w == 0) ? 0 : wsum[w - 1];
    g_start[i] = baseS + wofs + inc - v;
    g_rank[i]  = 0;
}

// ---------------- 3. per-relation fused gather + MLP + sorted store --------
// Two 16-row tiles per block (blockDim = D): threads [0, D/2) process tile 0,
// [D/2, D) tile 1. Each thread owns two adjacent columns (2c2, 2c2+1), so one
// broadcast LDS.128 feeds 32 fma2 (2x the 1-col kernel). z overwrites xs in
// place after a barrier (halves smem -> 8 blocks/SM at D=128).
template <int D, int A, int R>
__global__ void __launch_bounds__(D, 1024 / D)
msg_kernel(const float* __restrict__ emb,
           const float* __restrict__ rw, const float* __restrict__ rb,
           const float* __restrict__ ow, const float* __restrict__ ob,
           int idx_ofs) {
    constexpr int R2   = R / 2;
    constexpr int HALF = D / 2;
    __shared__ __align__(16) float xs[2][R2][2 * D];   // x, then z in-place
    __shared__ int idxS[2 * R * A];
    __shared__ int posS[2 * R * A];
    const int tid   = threadIdx.x;
    const int half  = tid / HALF;        // which tile
    const int c2    = tid % HALF;
    const int col   = 2 * c2;
    const int j     = col >> 6;          // which index within tuple
    const int e     = col & 63;          // even
    const int t0    = blockIdx.x * (2 * R);
    const int rbase = half * R;          // local tuple base for this tile

    // one thread per message row: node + fused rank (segment order arbitrary)
    if (tid < 2 * R * A) {
        int node = g_idx[idx_ofs + t0 * A + tid];
        idxS[tid] = node;
        posS[tid] = g_start[node] + atomicAdd(&g_rank[node], 1);
    }
    __syncthreads();

    // gather row pairs into this tile's smem slice
#pragma unroll
    for (int p = 0; p < R2; ++p) {
        int n0 = idxS[(rbase + 2 * p) * A + j];
        int n1 = idxS[(rbase + 2 * p + 1) * A + j];
        float2 a = *(const float2*)&emb[(size_t)n0 * EDIM + e];
        float2 b = *(const float2*)&emb[(size_t)n1 * EDIM + e];
        *(float4*)&xs[half][p][4 * c2] = make_float4(a.x, b.x, a.y, b.y);
    }
    __syncthreads();

    ull acc0[R2], acc1[R2];    // acc0: col, acc1: col+1 (rows packed in f32x2)
    // ---- h = x @ rw + rb ----
    {
        float2 b = *(const float2*)&rb[col];
#pragma unroll
        for (int p = 0; p < R2; ++p) { acc0[p] = dup2(b.x); acc1[p] = dup2(b.y); }
    }
#pragma unroll 4
    for (int k = 0; k < D; k += 2) {
        float2 wk0 = *(const float2*)&rw[(k + 0) * D + col];
        float2 wk1 = *(const float2*)&rw[(k + 1) * D + col];
        ull wA = dup2(wk0.x), wB = dup2(wk0.y);
        ull wC = dup2(wk1.x), wDd = dup2(wk1.y);
#pragma unroll
        for (int p = 0; p < R2; ++p) {
            ulonglong2 x2 = *(const ulonglong2*)&xs[half][p][2 * k];
            fma2(acc0[p], x2.x, wA);
            fma2(acc1[p], x2.x, wB);
            fma2(acc0[p], x2.y, wC);
            fma2(acc1[p], x2.y, wDd);
        }
    }
    __syncthreads();   // all GEMM1 reads of xs complete before overwrite

    // ---- z = x + mish(h), written in place over xs ----
#pragma unroll
    for (int p = 0; p < R2; ++p) {
        float h00, h01, h10, h11;
        unpack2(acc0[p], h00, h01);   // (row2p,col), (row2p+1,col)
        unpack2(acc1[p], h10, h11);   // (row2p,col+1), (row2p+1,col+1)
        float4 xv = *(const float4*)&xs[half][p][4 * c2];
        float4 v;
        v.x = xv.x + mishf(h00);
        v.y = xv.y + mishf(h01);
        v.z = xv.z + mishf(h10);
        v.w = xv.w + mishf(h11);
        *(float4*)&xs[half][p][4 * c2] = v;
    }
    __syncthreads();

    // ---- out = z @ ow + ob ----
    {
        float2 b = *(const float2*)&ob[col];
#pragma unroll
        for (int p = 0; p < R2; ++p) { acc0[p] = dup2(b.x); acc1[p] = dup2(b.y); }
    }
#pragma unroll 4
    for (int k = 0; k < D; k += 2) {
        float2 wk0 = *(const float2*)&ow[(k + 0) * D + col];
        float2 wk1 = *(const float2*)&ow[(k + 1) * D + col];
        ull wA = dup2(wk0.x), wB = dup2(wk0.y);
        ull wC = dup2(wk1.x), wDd = dup2(wk1.y);
#pragma unroll
        for (int p = 0; p < R2; ++p) {
            ulonglong2 z2 = *(const ulonglong2*)&xs[half][p][2 * k];
            fma2(acc0[p], z2.x, wA);
            fma2(acc1[p], z2.x, wB);
            fma2(acc0[p], z2.y, wC);
            fma2(acc1[p], z2.y, wDd);
        }
    }

    // ---- store message rows at node-sorted slots (pos from smem) ----
#pragma unroll
    for (int p = 0; p < R2; ++p) {
        float o00, o01, o10, o11;
        unpack2(acc0[p], o00, o01);
        unpack2(acc1[p], o10, o11);
        int p0 = posS[(rbase + 2 * p) * A + j];
        int p1 = posS[(rbase + 2 * p + 1) * A + j];
        *(float2*)&g_msg[(size_t)p0 * EDIM + e] = make_float2(o00, o10);
        *(float2*)&g_msg[(size_t)p1 * EDIM + e] = make_float2(o01, o11);
    }
}

// ---------------- 4. segment softmax-reduce (single pass, online) ----------
__global__ void reduce_kernel() {
    int node = (blockIdx.x * blockDim.x + threadIdx.x) >> 5;
    if (node >= N_NODES) return;
    const int lane  = threadIdx.x & 31;
    const int start = g_start[node];
    const int end   = start + g_cnt[node];
    const float base = g_flag[node] ? -INFINITY : 0.0f;

    float m0 = base, m1 = base;
    float s0 = 0.0f, s1 = 0.0f;
    for (int r = start; r < end; ++r) {
        const float* row = &g_msg[(size_t)r * EDIM];
        float v0 = row[lane], v1 = row[lane + 32];
        float n0 = fmaxf(m0, v0), n1 = fmaxf(m1, v1);
        s0 = s0 * expf(12.0f * (m0 - n0)) + expf(12.0f * (v0 - n0));
        s1 = s1 * expf(12.0f * (m1 - n1)) + expf(12.0f * (v1 - n1));
        m0 = n0; m1 = n1;
    }
    s0 += 1e-16f; s1 += 1e-16f;
    size_t o = (size_t)node * EDIM;
    g_mf[o + lane]      = logf(s0) * (1.0f / 12.0f) + m0;
    g_mf[o + lane + 32] = logf(s1) * (1.0f / 12.0f) + m1;
    if (lane == 0) { g_cnt[node] = 0; g_flag[node] = 0; }   // ready for next replay
}

// ---------------- 5. node update MLP (two-tile 2-col): [mf|emb](128)->64 ---
// Two tiles of 16 nodes per 128-thread block (32 nodes/block). GEMM1 (K=128,
// N=128): half-thread owns cols (2c2, 2c2+1); one broadcast LDS.128 feeds
// 32 fma2. z overwrites xs in place. GEMM2 (K=128, N=64): one col per thread.
template <int R>
__global__ void __launch_bounds__(128, 8)
update_kernel(const float* __restrict__ emb,
              const float* __restrict__ rw, const float* __restrict__ rb,
              const float* __restrict__ ow, const float* __restrict__ ob,
              float* __restrict__ out) {
    constexpr int R2 = R / 2;
    __shared__ __align__(16) float xs[2][R2][256];   // x, then z in-place
    const int tid  = threadIdx.x;
    const int half = tid >> 6;          // which tile
    const int c2   = tid & 63;
    const int col  = 2 * c2;            // 0..126, even
    const int n0g  = blockIdx.x * (2 * R) + half * R;

    // gather [mf | emb] row pairs (col, col+1 same source since col even)
#pragma unroll
    for (int p = 0; p < R2; ++p) {
        int nA = n0g + 2 * p, nB = n0g + 2 * p + 1;
        float2 a, b;
        if (col < 64) {
            a = *(const float2*)&g_mf[(size_t)nA * EDIM + col];
            b = *(const float2*)&g_mf[(size_t)nB * EDIM + col];
        } else {
            a = *(const float2*)&emb[(size_t)nA * EDIM + (col - 64)];
            b = *(const float2*)&emb[(size_t)nB * EDIM + (col - 64)];
        }
        *(float4*)&xs[half][p][4 * c2] = make_float4(a.x, b.x, a.y, b.y);
    }
    __syncthreads();

    ull acc0[R2], acc1[R2];
    // ---- h = x @ rw + rb ----
    {
        float2 b = *(const float2*)&rb[col];
#pragma unroll
        for (int p = 0; p < R2; ++p) { acc0[p] = dup2(b.x); acc1[p] = dup2(b.y); }
    }
#pragma unroll 4
    for (int k = 0; k < 128; k += 2) {
        float2 wk0 = *(const float2*)&rw[(k + 0) * 128 + col];
        float2 wk1 = *(const float2*)&rw[(k + 1) * 128 + col];
        ull wA = dup2(wk0.x), wB = dup2(wk0.y);
        ull wC = dup2(wk1.x), wDd = dup2(wk1.y);
#pragma unroll
        for (int p = 0; p < R2; ++p) {
            ulonglong2 x2 = *(const ulonglong2*)&xs[half][p][2 * k];
            fma2(acc0[p], x2.x, wA);
            fma2(acc1[p], x2.x, wB);
            fma2(acc0[p], x2.y, wC);
            fma2(acc1[p], x2.y, wDd);
        }
    }
    __syncthreads();

    // ---- z = x + mish(h), in place ----
#pragma unroll
    for (int p = 0; p < R2; ++p) {
        float h00, h01, h10, h11;
        unpack2(acc0[p], h00, h01);
        unpack2(acc1[p], h10, h11);
        float4 xv = *(const float4*)&xs[half][p][4 * c2];
        float4 v;
        v.x = xv.x + mishf(h00);
        v.y = xv.y + mishf(h01);
        v.z = xv.z + mishf(h10);
        v.w = xv.w + mishf(h11);
        *(float4*)&xs[half][p][4 * c2] = v;
    }
    __syncthreads();

    // ---- out = z @ ow + ob (N=64; one col per thread per tile) ----
    {
        ull a2[R2];
        float bc = ob[c2];
#pragma unroll
        for (int p = 0; p < R2; ++p) a2[p] = dup2(bc);
#pragma unroll 4
        for (int k = 0; k < 128; k += 2) {
            ull w0 = dup2(ow[(k + 0) * 64 + c2]);
            ull w1 = dup2(ow[(k + 1) * 64 + c2]);
#pragma unroll
            for (int p = 0; p < R2; ++p) {
                ulonglong2 z2 = *(const ulonglong2*)&xs[half][p][2 * k];
                fma2(a2[p], z2.x, w0);
                fma2(a2[p], z2.y, w1);
            }
        }
#pragma unroll
        for (int p = 0; p < R2; ++p) {
            float o0, o1;
            unpack2(a2[p], o0, o1);
            out[(size_t)(n0g + 2 * p + 0) * EDIM + c2] = o0;
            out[(size_t)(n0g + 2 * p + 1) * EDIM + c2] = o1;
        }
    }
}

// ---------------- launcher ----------------
extern "C" void kernel_launch(void* const* d_in, const int* in_sizes, int n_in,
                              void* d_out, int out_size) {
    const float* emb = (const float*)d_in[0];
    const void*  i0  = d_in[1];
    const void*  i1  = d_in[2];
    const void*  i2  = d_in[3];
    const float* r0rw = (const float*)d_in[4];
    const float* r0rb = (const float*)d_in[5];
    const float* r0ow = (const float*)d_in[6];
    const float* r0ob = (const float*)d_in[7];
    const float* r1rw = (const float*)d_in[8];
    const float* r1rb = (const float*)d_in[9];
    const float* r1ow = (const float*)d_in[10];
    const float* r1ob = (const float*)d_in[11];
    const float* r2rw = (const float*)d_in[12];
    const float* r2rb = (const float*)d_in[13];
    const float* r2ow = (const float*)d_in[14];
    const float* r2ob = (const float*)d_in[15];
    const float* urw  = (const float*)d_in[16];
    const float* urb  = (const float*)d_in[17];
    const float* uow  = (const float*)d_in[18];
    const float* uob  = (const float*)d_in[19];
    float* out = (float*)d_out;

    // prelude (3 launches)
    convhist_kernel<<<(NROWS + 255) / 256, 256>>>(i0, i1, i2);
    scanA_kernel<<<SCAN_BLOCKS, 256>>>();
    scanBC_kernel<<<SCAN_BLOCKS, 256>>>();

    // launch #4 = msg<128> (lands in the ncu capture window)
    // each block covers 2*R = 32 tuples
    msg_kernel<128, 2, 16><<<(L1 / 2) / 32, 128>>>(emb, r1rw, r1rb, r1ow, r1ob, L0);
    msg_kernel< 64, 1, 16><<<(L0 / 1) / 32,  64>>>(emb, r0rw, r0rb, r0ow, r0ob, 0);
    msg_kernel<192, 3, 16><<<(L2 / 3) / 32, 192>>>(emb, r2rw, r2rb, r2ow, r2ob, L0 + L1);

    // single-pass segment softmax-reduce, then node update (32 nodes/block)
    reduce_kernel<<<(N_NODES * 32 + 255) / 256, 256>>>();
    update_kernel<16><<<N_NODES / 32, 128>>>(emb, urw, urb, uow, uob, out);
}

// round 16
// speedup vs baseline: 1.6184x; 1.0335x over previous
#include <cuda_runtime.h>
#include <math.h>
#include <stdint.h>

// ---------------- problem constants (fixed shapes) ----------------
#define N_NODES 131072
#define EDIM    64
#define L0      262144
#define L1      524288
#define L2      393216
#define NROWS   (L0 + L1 + L2)   // 1179648
#define SCAN_BLOCKS 512          // N_NODES / 256

// ---------------- scratch (device globals; no cudaMalloc allowed) ----------
__device__ float g_msg[(size_t)NROWS * EDIM];     // node-sorted message rows
__device__ float g_mf [(size_t)N_NODES * EDIM];   // final max_msg per node
__device__ int   g_idx[NROWS];
__device__ int   g_cnt[N_NODES];                  // zero at load; reduce re-zeroes
__device__ int   g_start[N_NODES];
__device__ int   g_rank[N_NODES];                 // zeroed by scanBC each run
__device__ int   g_flag[N_NODES];                 // zero at load; reduce re-zeroes
__device__ int   g_bsum[SCAN_BLOCKS];

// ---------------- helpers ----------------
__device__ __forceinline__ float mishf(float x) {
    float sp = (x > 20.0f) ? x : log1pf(expf(x));
    return x * tanhf(sp);
}

// ---- packed f32x2 FMA (ptxas never emits FFMA2 from C++; PTX-only) ----
typedef unsigned long long ull;
__device__ __forceinline__ ull dup2(float w) {
    ull d;
    asm("mov.b64 %0, {%1, %1};" : "=l"(d) : "f"(w));
    return d;
}
__device__ __forceinline__ void fma2(ull& acc, ull x, ull w) {
    asm("fma.rn.f32x2 %0, %1, %2, %3;" : "=l"(acc) : "l"(x), "l"(w), "l"(acc));
}
__device__ __forceinline__ void unpack2(ull v, float& lo, float& hi) {
    asm("mov.b64 {%0, %1}, %2;" : "=f"(lo), "=f"(hi) : "l"(v));
}

// ---------------- 1. convert + histogram + rel0 flag (inline dtype detect) -
__global__ void convhist_kernel(const void* __restrict__ p0,
                                const void* __restrict__ p1,
                                const void* __restrict__ p2) {
    __shared__ int modeS;
    if (threadIdx.x < 32) {
        unsigned v = 0;
        if (threadIdx.x < 16) v = ((const unsigned*)p0)[threadIdx.x * 2 + 1];
        unsigned any = __ballot_sync(0xffffffffu, v != 0);
        if (threadIdx.x == 0) modeS = any ? 1 : 0;   // 1 = int32 data
    }
    __syncthreads();
    const int mode = modeS;

    int i = blockIdx.x * 256 + threadIdx.x;
    if (i >= NROWS) return;
    const void* p; int o;
    if      (i < L0)      { p = p0; o = i; }
    else if (i < L0 + L1) { p = p1; o = i - L0; }
    else                  { p = p2; o = i - L0 - L1; }
    int v;
    if (mode) v = ((const int*)p)[o];
    else      v = (int)(((const long long*)p)[o]);
    g_idx[i] = v;
    atomicAdd(&g_cnt[v], 1);
    if (i < L0) g_flag[v] = 1;   // racy identical writes: benign
}

// ---------------- 2a. per-block (256 nodes) sums ----------------
__global__ void scanA_kernel() {
    __shared__ int wsum[8];
    const int t = threadIdx.x;
    int v = g_cnt[blockIdx.x * 256 + t];
#pragma unroll
    for (int s = 16; s > 0; s >>= 1) v += __shfl_down_sync(0xffffffffu, v, s);
    if ((t & 31) == 0) wsum[t >> 5] = v;
    __syncthreads();
    if (t < 8) {
        int x = wsum[t];
#pragma unroll
        for (int s = 4; s > 0; s >>= 1) x += __shfl_down_sync(0xffu, x, s);
        if (t == 0) g_bsum[blockIdx.x] = x;
    }
}

// ---------------- 2b. base offset (masked reduce) + local scan --------------
__global__ void scanBC_kernel() {
    __shared__ int wsum[8];
    __shared__ int baseS;
    const int t = threadIdx.x;
    const int lane = t & 31, w = t >> 5;
    const int b = blockIdx.x;

    {
        int j0 = 2 * t, j1 = 2 * t + 1;
        int v = ((j0 < b) ? g_bsum[j0] : 0) + ((j1 < b) ? g_bsum[j1] : 0);
#pragma unroll
        for (int s = 16; s > 0; s >>= 1) v += __shfl_down_sync(0xffffffffu, v, s);
        if (lane == 0) wsum[w] = v;
        __syncthreads();
        if (t < 8) {
            int x = wsum[t];
#pragma unroll
            for (int s = 4; s > 0; s >>= 1) x += __shfl_down_sync(0xffu, x, s);
            if (t == 0) baseS = x;
        }
        __syncthreads();
    }

    const int i = b * 256 + t;
    int v = g_cnt[i];
    int inc = v;
#pragma unroll
    for (int s = 1; s < 32; s <<= 1) {
        int u = __shfl_up_sync(0xffffffffu, inc, s);
        if (lane >= s) inc += u;
    }
    __syncthreads();
    if (lane == 31) wsum[w] = inc;
    __syncthreads();
    if (t < 8) {
        int x = wsum[t];
#pragma unroll
        for (int s = 1; s < 8; s <<= 1) {
            int u = __shfl_up_sync(0xffu, x, s);
            if (t >= s) x += u;
        }
        wsum[t] = x;
    }
    __syncthreads();
    int wofs = (w == 0) ? 0 : wsum[w - 1];
    g_start[i] = baseS + wofs + inc - v;
    g_rank[i]  = 0;
}

// ---------------- 3. per-relation fused gather + MLP + sorted store --------
// Four 8-row tiles per block (blockDim = D, D/4 threads per tile). Each
// thread owns four adjacent columns (4c4..4c4+3): per 2 k-steps, 2 LDG.128
// (weights) + 4 LDS.128 (x pairs) feed 32 fma2 (6 L1 ops vs 10 in 2-col).
// Row pairs packed in f32x2 lanes: xs[tile][p][2k+h] = elem k of rows
// (2p, 2p+1). z overwrites xs in place after a barrier.
template <int D, int A, int R>   // R rows per tile; 4 tiles -> 4R rows/block
__global__ void __launch_bounds__(D, 1024 / D)
msg_kernel(const float* __restrict__ emb,
           const float* __restrict__ rw, const float* __restrict__ rb,
           const float* __restrict__ ow, const float* __restrict__ ob,
           int idx_ofs) {
    constexpr int R2  = R / 2;          // 4
    constexpr int TPT = D / 4;          // threads per tile
    __shared__ __align__(16) float xs[4][R2][2 * D];   // x, then z in-place
    __shared__ int idxS[4 * R * A];
    __shared__ int posS[4 * R * A];
    const int tid   = threadIdx.x;
    const int tile  = tid / TPT;
    const int c4    = tid % TPT;
    const int col   = 4 * c4;
    const int j     = col >> 6;          // which index within tuple
    const int e     = col & 63;          // multiple of 4
    const int t0    = blockIdx.x * (4 * R);
    const int rbase = tile * R;          // local tuple base for this tile

    // one thread per message row: node + fused rank (segment order arbitrary)
    if (tid < 4 * R * A) {
        int node = g_idx[idx_ofs + t0 * A + tid];
        idxS[tid] = node;
        posS[tid] = g_start[node] + atomicAdd(&g_rank[node], 1);
    }
    __syncthreads();

    // gather row pairs into this tile's smem slice (k = col..col+3)
#pragma unroll
    for (int p = 0; p < R2; ++p) {
        int n0 = idxS[(rbase + 2 * p) * A + j];
        int n1 = idxS[(rbase + 2 * p + 1) * A + j];
        float4 a = *(const float4*)&emb[(size_t)n0 * EDIM + e];
        float4 b = *(const float4*)&emb[(size_t)n1 * EDIM + e];
        *(float4*)&xs[tile][p][8 * c4]     = make_float4(a.x, b.x, a.y, b.y);
        *(float4*)&xs[tile][p][8 * c4 + 4] = make_float4(a.z, b.z, a.w, b.w);
    }
    __syncthreads();

    ull acc[4][R2];    // [col q][row pair p], rows packed in f32x2
    // ---- h = x @ rw + rb ----
    {
        float4 b = *(const float4*)&rb[col];
#pragma unroll
        for (int p = 0; p < R2; ++p) {
            acc[0][p] = dup2(b.x); acc[1][p] = dup2(b.y);
            acc[2][p] = dup2(b.z); acc[3][p] = dup2(b.w);
        }
    }
#pragma unroll 2
    for (int k = 0; k < D; k += 2) {
        float4 w0 = *(const float4*)&rw[(k + 0) * D + col];
        float4 w1 = *(const float4*)&rw[(k + 1) * D + col];
        ull W00 = dup2(w0.x), W01 = dup2(w0.y), W02 = dup2(w0.z), W03 = dup2(w0.w);
        ull W10 = dup2(w1.x), W11 = dup2(w1.y), W12 = dup2(w1.z), W13 = dup2(w1.w);
#pragma unroll
        for (int p = 0; p < R2; ++p) {
            ulonglong2 x2 = *(const ulonglong2*)&xs[tile][p][2 * k];
            fma2(acc[0][p], x2.x, W00);
            fma2(acc[1][p], x2.x, W01);
            fma2(acc[2][p], x2.x, W02);
            fma2(acc[3][p], x2.x, W03);
            fma2(acc[0][p], x2.y, W10);
            fma2(acc[1][p], x2.y, W11);
            fma2(acc[2][p], x2.y, W12);
            fma2(acc[3][p], x2.y, W13);
        }
    }
    __syncthreads();   // all GEMM1 reads of xs complete before overwrite

    // ---- z = x + mish(h), written in place over xs ----
#pragma unroll
    for (int p = 0; p < R2; ++p) {
        float h0a, h0b, h1a, h1b, h2a, h2b, h3a, h3b;
        unpack2(acc[0][p], h0a, h0b);   // col+0: rows (2p, 2p+1)
        unpack2(acc[1][p], h1a, h1b);
        unpack2(acc[2][p], h2a, h2b);
        unpack2(acc[3][p], h3a, h3b);
        float4 lo = *(const float4*)&xs[tile][p][8 * c4];      // cols 0,1
        float4 hi = *(const float4*)&xs[tile][p][8 * c4 + 4];  // cols 2,3
        lo.x += mishf(h0a); lo.y += mishf(h0b);
        lo.z += mishf(h1a); lo.w += mishf(h1b);
        hi.x += mishf(h2a); hi.y += mishf(h2b);
        hi.z += mishf(h3a); hi.w += mishf(h3b);
        *(float4*)&xs[tile][p][8 * c4]     = lo;
        *(float4*)&xs[tile][p][8 * c4 + 4] = hi;
    }
    __syncthreads();

    // ---- out = z @ ow + ob ----
    {
        float4 b = *(const float4*)&ob[col];
#pragma unroll
        for (int p = 0; p < R2; ++p) {
            acc[0][p] = dup2(b.x); acc[1][p] = dup2(b.y);
            acc[2][p] = dup2(b.z); acc[3][p] = dup2(b.w);
        }
    }
#pragma unroll 2
    for (int k = 0; k < D; k += 2) {
        float4 w0 = *(const float4*)&ow[(k + 0) * D + col];
        float4 w1 = *(const float4*)&ow[(k + 1) * D + col];
        ull W00 = dup2(w0.x), W01 = dup2(w0.y), W02 = dup2(w0.z), W03 = dup2(w0.w);
        ull W10 = dup2(w1.x), W11 = dup2(w1.y), W12 = dup2(w1.z), W13 = dup2(w1.w);
#pragma unroll
        for (int p = 0; p < R2; ++p) {
            ulonglong2 z2 = *(const ulonglong2*)&xs[tile][p][2 * k];
            fma2(acc[0][p], z2.x, W00);
            fma2(acc[1][p], z2.x, W01);
            fma2(acc[2][p], z2.x, W02);
            fma2(acc[3][p], z2.x, W03);
            fma2(acc[0][p], z2.y, W10);
            fma2(acc[1][p], z2.y, W11);
            fma2(acc[2][p], z2.y, W12);
            fma2(acc[3][p], z2.y, W13);
        }
    }

    // ---- store message rows at node-sorted slots (pos from smem) ----
#pragma unroll
    for (int p = 0; p < R2; ++p) {
        float o0a, o0b, o1a, o1b, o2a, o2b, o3a, o3b;
        unpack2(acc[0][p], o0a, o0b);
        unpack2(acc[1][p], o1a, o1b);
        unpack2(acc[2][p], o2a, o2b);
        unpack2(acc[3][p], o3a, o3b);
        int p0 = posS[(rbase + 2 * p) * A + j];
        int p1 = posS[(rbase + 2 * p + 1) * A + j];
        *(float4*)&g_msg[(size_t)p0 * EDIM + e] = make_float4(o0a, o1a, o2a, o3a);
        *(float4*)&g_msg[(size_t)p1 * EDIM + e] = make_float4(o0b, o1b, o2b, o3b);
    }
}

// ---------------- 4. segment softmax-reduce (single pass, online) ----------
__global__ void reduce_kernel() {
    int node = (blockIdx.x * blockDim.x + threadIdx.x) >> 5;
    if (node >= N_NODES) return;
    const int lane  = threadIdx.x & 31;
    const int start = g_start[node];
    const int end   = start + g_cnt[node];
    const float base = g_flag[node] ? -INFINITY : 0.0f;

    float m0 = base, m1 = base;
    float s0 = 0.0f, s1 = 0.0f;
    for (int r = start; r < end; ++r) {
        const float* row = &g_msg[(size_t)r * EDIM];
        float v0 = row[lane], v1 = row[lane + 32];
        float n0 = fmaxf(m0, v0), n1 = fmaxf(m1, v1);
        s0 = s0 * expf(12.0f * (m0 - n0)) + expf(12.0f * (v0 - n0));
        s1 = s1 * expf(12.0f * (m1 - n1)) + expf(12.0f * (v1 - n1));
        m0 = n0; m1 = n1;
    }
    s0 += 1e-16f; s1 += 1e-16f;
    size_t o = (size_t)node * EDIM;
    g_mf[o + lane]      = logf(s0) * (1.0f / 12.0f) + m0;
    g_mf[o + lane + 32] = logf(s1) * (1.0f / 12.0f) + m1;
    if (lane == 0) { g_cnt[node] = 0; g_flag[node] = 0; }   // ready for next replay
}

// ---------------- 5. node update MLP (two-tile 2-col): [mf|emb](128)->64 ---
template <int R>
__global__ void __launch_bounds__(128, 8)
update_kernel(const float* __restrict__ emb,
              const float* __restrict__ rw, const float* __restrict__ rb,
              const float* __restrict__ ow, const float* __restrict__ ob,
              float* __restrict__ out) {
    constexpr int R2 = R / 2;
    __shared__ __align__(16) float xs[2][R2][256];   // x, then z in-place
    const int tid  = threadIdx.x;
    const int half = tid >> 6;          // which tile
    const int c2   = tid & 63;
    const int col  = 2 * c2;            // 0..126, even
    const int n0g  = blockIdx.x * (2 * R) + half * R;

    // gather [mf | emb] row pairs (col, col+1 same source since col even)
#pragma unroll
    for (int p = 0; p < R2; ++p) {
        int nA = n0g + 2 * p, nB = n0g + 2 * p + 1;
        float2 a, b;
        if (col < 64) {
            a = *(const float2*)&g_mf[(size_t)nA * EDIM + col];
            b = *(const float2*)&g_mf[(size_t)nB * EDIM + col];
        } else {
            a = *(const float2*)&emb[(size_t)nA * EDIM + (col - 64)];
            b = *(const float2*)&emb[(size_t)nB * EDIM + (col - 64)];
        }
        *(float4*)&xs[half][p][4 * c2] = make_float4(a.x, b.x, a.y, b.y);
    }
    __syncthreads();

    ull acc0[R2], acc1[R2];
    {
        float2 b = *(const float2*)&rb[col];
#pragma unroll
        for (int p = 0; p < R2; ++p) { acc0[p] = dup2(b.x); acc1[p] = dup2(b.y); }
    }
#pragma unroll 4
    for (int k = 0; k < 128; k += 2) {
        float2 wk0 = *(const float2*)&rw[(k + 0) * 128 + col];
        float2 wk1 = *(const float2*)&rw[(k + 1) * 128 + col];
        ull wA = dup2(wk0.x), wB = dup2(wk0.y);
        ull wC = dup2(wk1.x), wDd = dup2(wk1.y);
#pragma unroll
        for (int p = 0; p < R2; ++p) {
            ulonglong2 x2 = *(const ulonglong2*)&xs[half][p][2 * k];
            fma2(acc0[p], x2.x, wA);
            fma2(acc1[p], x2.x, wB);
            fma2(acc0[p], x2.y, wC);
            fma2(acc1[p], x2.y, wDd);
        }
    }
    __syncthreads();

#pragma unroll
    for (int p = 0; p < R2; ++p) {
        float h00, h01, h10, h11;
        unpack2(acc0[p], h00, h01);
        unpack2(acc1[p], h10, h11);
        float4 xv = *(const float4*)&xs[half][p][4 * c2];
        float4 v;
        v.x = xv.x + mishf(h00);
        v.y = xv.y + mishf(h01);
        v.z = xv.z + mishf(h10);
        v.w = xv.w + mishf(h11);
        *(float4*)&xs[half][p][4 * c2] = v;
    }
    __syncthreads();

    // ---- out = z @ ow + ob (N=64; one col per thread per tile) ----
    {
        ull a2[R2];
        float bc = ob[c2];
#pragma unroll
        for (int p = 0; p < R2; ++p) a2[p] = dup2(bc);
#pragma unroll 4
        for (int k = 0; k < 128; k += 2) {
            ull w0 = dup2(ow[(k + 0) * 64 + c2]);
            ull w1 = dup2(ow[(k + 1) * 64 + c2]);
#pragma unroll
            for (int p = 0; p < R2; ++p) {
                ulonglong2 z2 = *(const ulonglong2*)&xs[half][p][2 * k];
                fma2(a2[p], z2.x, w0);
                fma2(a2[p], z2.y, w1);
            }
        }
#pragma unroll
        for (int p = 0; p < R2; ++p) {
            float o0, o1;
            unpack2(a2[p], o0, o1);
            out[(size_t)(n0g + 2 * p + 0) * EDIM + c2] = o0;
            out[(size_t)(n0g + 2 * p + 1) * EDIM + c2] = o1;
        }
    }
}

// ---------------- launcher ----------------
extern "C" void kernel_launch(void* const* d_in, const int* in_sizes, int n_in,
                              void* d_out, int out_size) {
    const float* emb = (const float*)d_in[0];
    const void*  i0  = d_in[1];
    const void*  i1  = d_in[2];
    const void*  i2  = d_in[3];
    const float* r0rw = (const float*)d_in[4];
    const float* r0rb = (const float*)d_in[5];
    const float* r0ow = (const float*)d_in[6];
    const float* r0ob = (const float*)d_in[7];
    const float* r1rw = (const float*)d_in[8];
    const float* r1rb = (const float*)d_in[9];
    const float* r1ow = (const float*)d_in[10];
    const float* r1ob = (const float*)d_in[11];
    const float* r2rw = (const float*)d_in[12];
    const float* r2rb = (const float*)d_in[13];
    const float* r2ow = (const float*)d_in[14];
    const float* r2ob = (const float*)d_in[15];
    const float* urw  = (const float*)d_in[16];
    const float* urb  = (const float*)d_in[17];
    const float* uow  = (const float*)d_in[18];
    const float* uob  = (const float*)d_in[19];
    float* out = (float*)d_out;

    // prelude (3 launches)
    convhist_kernel<<<(NROWS + 255) / 256, 256>>>(i0, i1, i2);
    scanA_kernel<<<SCAN_BLOCKS, 256>>>();
    scanBC_kernel<<<SCAN_BLOCKS, 256>>>();

    // launch #4 = msg<128> (lands in the ncu capture window)
    // each block covers 4*R = 32 tuples
    msg_kernel<128, 2, 8><<<(L1 / 2) / 32, 128>>>(emb, r1rw, r1rb, r1ow, r1ob, L0);
    msg_kernel< 64, 1, 8><<<(L0 / 1) / 32,  64>>>(emb, r0rw, r0rb, r0ow, r0ob, 0);
    msg_kernel<192, 3, 8><<<(L2 / 3) / 32, 192>>>(emb, r2rw, r2rb, r2ow, r2ob, L0 + L1);

    // single-pass segment softmax-reduce, then node update (32 nodes/block)
    reduce_kernel<<<(N_NODES * 32 + 255) / 256, 256>>>();
    update_kernel<16><<<N_NODES / 32, 128>>>(emb, urw, urb, uow, uob, out);
}